// round 14
// baseline (speedup 1.0000x reference)
#include <cuda_runtime.h>
#include <cstdint>

// 64 steps of diffusion-advection on a 1024x1024 periodic grid, emitting
// (T, 3, H, W) fp32 RGB, as ONE persistent kernel (no prologue launch).
//
// At the measured roofline: 805 MB of mandatory frame output at ~5.07 TB/s
// effective DRAM write throughput. The per-step sync chain hides under the
// L2 dirty-backlog drain (T = max(write_drain, chain), write_drain binding).
//
//  - r channel of frame s == u_{s+1} exactly (clipped); frames carry state.
//  - Per-row monotonic flags, persistent across graph replays: each block
//    reads its own flag at entry as `base` (all flags equal at kernel start
//    since the prior launch fully completed; only this block ever writes its
//    flag), waits for neighbors >= base+s, publishes base+s+1. No reset.
//  - All-thread ld.acquire.gpu polling (one L2 line per block, coalesced;
//    validated fastest in R12).
//  - Only the r store precedes the flag publish; g/b (2/3 of traffic, never
//    read) drain after it via L2 writeback.
//  - Warp-edge x-neighbors via parity-double-buffered smem.
//  - 1024 blocks x 256 threads, 1 row/block, u in registers; <=32 regs ->
//    8 blocks/SM, 1184 slots >= 1024 blocks (spin-safe co-residency).

#define HH 1024
#define WW 1024
#define HW (HH * WW)

#define DT     0.1f
#define ALPHA  0.05f
#define V_X    0.1f
// V_Y == 0 -> du_dy term vanishes.

#define NB 1024
#define FS 32                 // flag stride in ints (128 B)

__device__ int g_flags[NB * FS];   // zero-initialized at module load

__device__ __forceinline__ int ld_acq(const int* p) {
    int v;
    asm volatile("ld.acquire.gpu.global.b32 %0, [%1];"
                 : "=r"(v) : "l"(p) : "memory");
    return v;
}
__device__ __forceinline__ void st_rel(int* p, int v) {
    asm volatile("st.release.gpu.global.b32 [%0], %1;"
                 :: "l"(p), "r"(v) : "memory");
}

__global__ __launch_bounds__(256, 8)
void physics_persistent_kernel(const float* __restrict__ u_init,
                               float* __restrict__ frames,
                               int n_frames)
{
    // Edge exchange: [parity][0=first elem of warp][wid], [1=last][wid]
    __shared__ float sEdge[2][2][8];

    const int y    = blockIdx.x;          // owned row
    const int c4   = threadIdx.x;         // float4 column 0..255
    const int lane = c4 & 31;
    const int wid  = c4 >> 5;
    const int ym1  = (y - 1) & (HH - 1);
    const int yp1  = (y + 1) & (HH - 1);

    const int idx  = (y   << 8) + c4;     // float4 index within a channel
    const int idxu = (ym1 << 8) + c4;
    const int idxd = (yp1 << 8) + c4;

    int*       flag_self = &g_flags[y   * FS];
    const int* flag_up   = &g_flags[ym1 * FS];
    const int* flag_dn   = &g_flags[yp1 * FS];

    // Monotonic flag base (replay-safe): all flags equal at kernel start.
    const int base = ld_acq(flag_self);

    float4 u = ((const float4*)u_init)[idx];   // u_s for own row
    const float* src = u_init;                 // where u_s lives (r of s-1)
    float*       fr  = frames;                 // frame s base

    if (lane == 0)  sEdge[0][0][wid] = u.x;
    if (lane == 31) sEdge[0][1][wid] = u.w;
    __syncthreads();

    for (int s = 0; s < n_frames; ++s) {
        if (s > 0) {
            const int tgt = base + s;
            while (ld_acq(flag_up) < tgt) { }
            while (ld_acq(flag_dn) < tgt) { }
        }

        const float4* src4 = (const float4*)src;
        const float4 hu = __ldcg(&src4[idxu]);
        const float4 hd = __ldcg(&src4[idxd]);

        const int par = s & 1;
        const float lwS = sEdge[par][1][(wid - 1) & 7];
        const float rxS = sEdge[par][0][(wid + 1) & 7];

        float lw = __shfl_up_sync(0xffffffffu, u.w, 1);
        float rx = __shfl_down_sync(0xffffffffu, u.x, 1);
        if (lane == 0)  lw = lwS;
        if (lane == 31) rx = rxS;

        const float uc[4] = {u.x,  u.y,  u.z,  u.w};
        const float ul[4] = {lw,   u.x,  u.y,  u.z};
        const float ur[4] = {u.y,  u.z,  u.w,  rx};
        const float uu[4] = {hu.x, hu.y, hu.z, hu.w};
        const float ud[4] = {hd.x, hd.y, hd.z, hd.w};

        float4 n;
        float* np = &n.x;
        #pragma unroll
        for (int i = 0; i < 4; ++i) {
            const float lap = ul[i] + ur[i] + uu[i] + ud[i] - 4.0f * uc[i];
            float v = uc[i] + DT * (ALPHA * lap - V_X * (uc[i] - ul[i]));
            np[i] = fminf(fmaxf(v, 0.0f), 1.0f);
        }

        float4* f4 = (float4*)fr;
        f4[idx] = n;                       // r channel: the only re-read data

        // Stage next step's edges (other parity slot; race-free).
        if (lane == 0)  sEdge[par ^ 1][0][wid] = n.x;
        if (lane == 31) sEdge[par ^ 1][1][wid] = n.w;

        // Publish: barrier (all r stores + edge STS ordered) -> release.
        __syncthreads();
        if (c4 == 0) st_rel(flag_self, base + s + 1);

        // g/b: never read by anyone -> off the critical chain; L2 writeback
        // drains them while the next step's chain runs.
        float4 t;
        t.x = n.x * 0.5f; t.y = n.y * 0.5f;
        t.z = n.z * 0.5f; t.w = n.w * 0.5f;
        f4[idx + (HW / 4)] = t;
        t.x = 1.0f - n.x; t.y = 1.0f - n.y;
        t.z = 1.0f - n.z; t.w = 1.0f - n.w;
        f4[idx + 2 * (HW / 4)] = t;

        u   = n;
        src = fr;          // r channel of frame s == u_{s+1}
        fr += 3 * HW;
    }
}

extern "C" void kernel_launch(void* const* d_in, const int* in_sizes, int n_in,
                              void* d_out, int out_size) {
    const float* init = (const float*)d_in[0];
    float* out = (float*)d_out;
    const int n_frames = out_size / (3 * HW);

    physics_persistent_kernel<<<NB, 256>>>(init, out, n_frames);
}

// round 15
// speedup vs baseline: 1.4665x; 1.4665x over previous
#include <cuda_runtime.h>
#include <cstdint>

// 64 steps of diffusion-advection on a 1024x1024 periodic grid, emitting
// (T, 3, H, W) fp32 RGB, as ONE persistent kernel. (Champion R12 structure,
// restored: reset prologue + all-thread constant-target polls + writeback
// g/b stores. Validated at ~160us across five structural variants = the
// effective DRAM write-stream roofline, ~5.07 TB/s for 805 MB of output.)
//
//  - r channel of frame s == u_{s+1} exactly (clipped); frames carry state.
//  - Per-row flags: producer block-bar + st.release.gpu; consumer
//    ld.acquire.gpu spin (fused two-neighbor poll: latencies overlap).
//  - Only the r store precedes the flag; g/b stores (2/3 of traffic, never
//    read) are issued after publish and drain via lazy L2 writeback.
//  - Warp-edge x-neighbors exchanged through parity-double-buffered smem.
//  - 1024 blocks x 256 threads, 1 row/block, u in registers; <=32 regs ->
//    8 blocks/SM, 1184 slots >= 1024 blocks (spin-safe co-residency).

#define HH 1024
#define WW 1024
#define HW (HH * WW)

#define DT     0.1f
#define ALPHA  0.05f
#define V_X    0.1f
// V_Y == 0 -> du_dy term vanishes.

#define NB 1024
#define FS 32                 // flag stride in ints (128 B)

__device__ int g_flags[NB * FS];

__global__ void reset_flags_kernel() {
    const int i = blockIdx.x * blockDim.x + threadIdx.x;   // 0..NB-1
    g_flags[i * FS] = 0;
}

__device__ __forceinline__ int ld_acq(const int* p) {
    int v;
    asm volatile("ld.acquire.gpu.global.b32 %0, [%1];"
                 : "=r"(v) : "l"(p) : "memory");
    return v;
}
__device__ __forceinline__ void st_rel(int* p, int v) {
    asm volatile("st.release.gpu.global.b32 [%0], %1;"
                 :: "l"(p), "r"(v) : "memory");
}

__global__ __launch_bounds__(256, 8)
void physics_persistent_kernel(const float* __restrict__ u_init,
                               float* __restrict__ frames,
                               int n_frames)
{
    // Edge exchange: [parity][0=first elem of warp][wid], [1=last][wid]
    __shared__ float sEdge[2][2][8];

    const int y    = blockIdx.x;          // owned row
    const int c4   = threadIdx.x;         // float4 column 0..255
    const int lane = c4 & 31;
    const int wid  = c4 >> 5;
    const int ym1  = (y - 1) & (HH - 1);
    const int yp1  = (y + 1) & (HH - 1);

    const int idx  = (y   << 8) + c4;     // float4 index within a channel
    const int idxu = (ym1 << 8) + c4;
    const int idxd = (yp1 << 8) + c4;

    int*       flag_self = &g_flags[y   * FS];
    const int* flag_up   = &g_flags[ym1 * FS];
    const int* flag_dn   = &g_flags[yp1 * FS];

    float4 u = ((const float4*)u_init)[idx];   // u_s for own row
    const float* src = u_init;                 // where u_s lives (r of s-1)
    float*       fr  = frames;                 // frame s base

    if (lane == 0)  sEdge[0][0][wid] = u.x;
    if (lane == 31) sEdge[0][1][wid] = u.w;
    __syncthreads();

    for (int s = 0; s < n_frames; ++s) {
        if (s > 0) {
            // Fused two-neighbor poll: both L2 reads in flight per trip.
            for (;;) {
                const int a = ld_acq(flag_up);
                const int b = ld_acq(flag_dn);
                if (a >= s && b >= s) break;
            }
        }

        const float4* src4 = (const float4*)src;
        const float4 hu = __ldcg(&src4[idxu]);
        const float4 hd = __ldcg(&src4[idxd]);

        const int par = s & 1;
        const float lwS = sEdge[par][1][(wid - 1) & 7];
        const float rxS = sEdge[par][0][(wid + 1) & 7];

        float lw = __shfl_up_sync(0xffffffffu, u.w, 1);
        float rx = __shfl_down_sync(0xffffffffu, u.x, 1);
        if (lane == 0)  lw = lwS;
        if (lane == 31) rx = rxS;

        const float uc[4] = {u.x,  u.y,  u.z,  u.w};
        const float ul[4] = {lw,   u.x,  u.y,  u.z};
        const float ur[4] = {u.y,  u.z,  u.w,  rx};
        const float uu[4] = {hu.x, hu.y, hu.z, hu.w};
        const float ud[4] = {hd.x, hd.y, hd.z, hd.w};

        float4 n;
        float* np = &n.x;
        #pragma unroll
        for (int i = 0; i < 4; ++i) {
            const float lap = ul[i] + ur[i] + uu[i] + ud[i] - 4.0f * uc[i];
            float v = uc[i] + DT * (ALPHA * lap - V_X * (uc[i] - ul[i]));
            np[i] = fminf(fmaxf(v, 0.0f), 1.0f);
        }

        float4* f4 = (float4*)fr;
        f4[idx] = n;                       // r channel: the only re-read data

        // Stage next step's edges (other parity slot; race-free).
        if (lane == 0)  sEdge[par ^ 1][0][wid] = n.x;
        if (lane == 31) sEdge[par ^ 1][1][wid] = n.w;

        // Publish: barrier (all r stores + edge STS ordered) -> release.
        __syncthreads();
        if (c4 == 0) st_rel(flag_self, s + 1);

        // g/b: never read by anyone -> off the critical chain; L2 writeback
        // drains them while the next step's chain runs.
        float4 t;
        t.x = n.x * 0.5f; t.y = n.y * 0.5f;
        t.z = n.z * 0.5f; t.w = n.w * 0.5f;
        f4[idx + (HW / 4)] = t;
        t.x = 1.0f - n.x; t.y = 1.0f - n.y;
        t.z = 1.0f - n.z; t.w = 1.0f - n.w;
        f4[idx + 2 * (HW / 4)] = t;

        u   = n;
        src = fr;          // r channel of frame s == u_{s+1}
        fr += 3 * HW;
    }
}

extern "C" void kernel_launch(void* const* d_in, const int* in_sizes, int n_in,
                              void* d_out, int out_size) {
    const float* init = (const float*)d_in[0];
    float* out = (float*)d_out;
    const int n_frames = out_size / (3 * HW);

    reset_flags_kernel<<<NB / 256, 256>>>();
    physics_persistent_kernel<<<NB, 256>>>(init, out, n_frames);
}

// round 16
// speedup vs baseline: 1.5084x; 1.0285x over previous
#include <cuda_runtime.h>
#include <cstdint>

// 64 steps of diffusion-advection on a 1024x1024 periodic grid, emitting
// (T, 3, H, W) fp32 RGB, as ONE persistent kernel.  (R7 structure, with
// plain writeback stores instead of __stcs: L2 acts as a pulse-smoothing
// write reservoir so DRAM stays fed during the per-step sync chain.)
//
//  - r channel of frame s == u_{s+1} exactly (clipped); frames carry state.
//  - Per-row flags: producer block-bar + st.release.gpu; consumer
//    ld.acquire.gpu spin. One __syncthreads per step.
//  - Only the r store precedes the flag; g/b stores (2/3 of traffic, never
//    read) are issued after publish and drain via lazy L2 writeback.
//  - Warp-edge x-neighbors exchanged through parity-double-buffered smem.
//  - 1024 blocks x 256 threads, 1 row/block, u in registers; <=32 regs ->
//    8 blocks/SM, 1184 slots >= 1024 blocks (spin-safe co-residency).

#define HH 1024
#define WW 1024
#define HW (HH * WW)

#define DT     0.1f
#define ALPHA  0.05f
#define V_X    0.1f
// V_Y == 0 -> du_dy term vanishes.

#define NB 1024
#define FS 32                 // flag stride in ints (128 B)

__device__ int g_flags[NB * FS];

__global__ void reset_flags_kernel() {
    const int i = blockIdx.x * blockDim.x + threadIdx.x;   // 0..NB-1
    g_flags[i * FS] = 0;
}

__device__ __forceinline__ int ld_acq(const int* p) {
    int v;
    asm volatile("ld.acquire.gpu.global.b32 %0, [%1];"
                 : "=r"(v) : "l"(p) : "memory");
    return v;
}
__device__ __forceinline__ void st_rel(int* p, int v) {
    asm volatile("st.release.gpu.global.b32 [%0], %1;"
                 :: "l"(p), "r"(v) : "memory");
}

__global__ __launch_bounds__(256, 8)
void physics_persistent_kernel(const float* __restrict__ u_init,
                               float* __restrict__ frames,
                               int n_frames)
{
    // Edge exchange: [parity][0=first elem of warp][wid], [1=last][wid]
    __shared__ float sEdge[2][2][8];

    const int y    = blockIdx.x;          // owned row
    const int c4   = threadIdx.x;         // float4 column 0..255
    const int lane = c4 & 31;
    const int wid  = c4 >> 5;
    const int ym1  = (y - 1) & (HH - 1);
    const int yp1  = (y + 1) & (HH - 1);

    const int idx  = (y   << 8) + c4;     // float4 index within a channel
    const int idxu = (ym1 << 8) + c4;
    const int idxd = (yp1 << 8) + c4;

    int*       flag_self = &g_flags[y   * FS];
    const int* flag_up   = &g_flags[ym1 * FS];
    const int* flag_dn   = &g_flags[yp1 * FS];

    float4 u = ((const float4*)u_init)[idx];   // u_s for own row
    const float* src = u_init;                 // where u_s lives (r of s-1)
    float*       fr  = frames;                 // frame s base

    if (lane == 0)  sEdge[0][0][wid] = u.x;
    if (lane == 31) sEdge[0][1][wid] = u.w;
    __syncthreads();

    for (int s = 0; s < n_frames; ++s) {
        if (s > 0) {
            while (ld_acq(flag_up) < s) { }
            while (ld_acq(flag_dn) < s) { }
        }

        const float4* src4 = (const float4*)src;
        const float4 hu = __ldcg(&src4[idxu]);
        const float4 hd = __ldcg(&src4[idxd]);

        const int par = s & 1;
        const float lwS = sEdge[par][1][(wid - 1) & 7];
        const float rxS = sEdge[par][0][(wid + 1) & 7];

        float lw = __shfl_up_sync(0xffffffffu, u.w, 1);
        float rx = __shfl_down_sync(0xffffffffu, u.x, 1);
        if (lane == 0)  lw = lwS;
        if (lane == 31) rx = rxS;

        const float uc[4] = {u.x,  u.y,  u.z,  u.w};
        const float ul[4] = {lw,   u.x,  u.y,  u.z};
        const float ur[4] = {u.y,  u.z,  u.w,  rx};
        const float uu[4] = {hu.x, hu.y, hu.z, hu.w};
        const float ud[4] = {hd.x, hd.y, hd.z, hd.w};

        float4 n;
        float* np = &n.x;
        #pragma unroll
        for (int i = 0; i < 4; ++i) {
            const float lap = ul[i] + ur[i] + uu[i] + ud[i] - 4.0f * uc[i];
            float v = uc[i] + DT * (ALPHA * lap - V_X * (uc[i] - ul[i]));
            np[i] = fminf(fmaxf(v, 0.0f), 1.0f);
        }

        float4* f4 = (float4*)fr;
        f4[idx] = n;                       // r channel: the only re-read data

        // Stage next step's edges (other parity slot; race-free).
        if (lane == 0)  sEdge[par ^ 1][0][wid] = n.x;
        if (lane == 31) sEdge[par ^ 1][1][wid] = n.w;

        // Publish: barrier (all r stores + edge STS ordered) -> release.
        __syncthreads();
        if (c4 == 0) st_rel(flag_self, s + 1);

        // g/b: never read by anyone -> off the critical chain. Plain
        // writeback stores: L2 buffers the pulse and drains continuously.
        float4 t;
        t.x = n.x * 0.5f; t.y = n.y * 0.5f;
        t.z = n.z * 0.5f; t.w = n.w * 0.5f;
        f4[idx + (HW / 4)] = t;
        t.x = 1.0f - n.x; t.y = 1.0f - n.y;
        t.z = 1.0f - n.z; t.w = 1.0f - n.w;
        f4[idx + 2 * (HW / 4)] = t;

        u   = n;
        src = fr;          // r channel of frame s == u_{s+1}
        fr += 3 * HW;
    }
}

extern "C" void kernel_launch(void* const* d_in, const int* in_sizes, int n_in,
                              void* d_out, int out_size) {
    const float* init = (const float*)d_in[0];
    float* out = (float*)d_out;
    const int n_frames = out_size / (3 * HW);

    reset_flags_kernel<<<NB / 256, 256>>>();
    physics_persistent_kernel<<<NB, 256>>>(init, out, n_frames);
}

// round 17
// speedup vs baseline: 1.5123x; 1.0026x over previous
#include <cuda_runtime.h>
#include <cstdint>

// 64 steps of diffusion-advection on a 1024x1024 periodic grid, emitting
// (T, 3, H, W) fp32 RGB, as ONE persistent kernel. Champion structure
// (R12/R16, ~160us = DRAM write-stream roofline), with one chain trim:
// the up-halo load is hoisted between the two spin loops so its L2 latency
// overlaps the down-neighbor spin.
//
//  - r channel of frame s == u_{s+1} exactly (clipped); frames carry state.
//  - Per-row flags: producer block-bar + st.release.gpu; consumer
//    ld.acquire.gpu spin (two sequential loops — validated protocol).
//  - Only the r store precedes the flag; g/b stores (2/3 of traffic, never
//    read) are issued after publish and drain via lazy L2 writeback.
//  - Warp-edge x-neighbors exchanged through parity-double-buffered smem.
//  - 1024 blocks x 256 threads, 1 row/block, u in registers; <=32 regs ->
//    8 blocks/SM, 1184 slots >= 1024 blocks (spin-safe co-residency).

#define HH 1024
#define WW 1024
#define HW (HH * WW)

#define DT     0.1f
#define ALPHA  0.05f
#define V_X    0.1f
// V_Y == 0 -> du_dy term vanishes.

#define NB 1024
#define FS 32                 // flag stride in ints (128 B)

__device__ int g_flags[NB * FS];

__global__ void reset_flags_kernel() {
    const int i = blockIdx.x * blockDim.x + threadIdx.x;   // 0..NB-1
    g_flags[i * FS] = 0;
}

__device__ __forceinline__ int ld_acq(const int* p) {
    int v;
    asm volatile("ld.acquire.gpu.global.b32 %0, [%1];"
                 : "=r"(v) : "l"(p) : "memory");
    return v;
}
__device__ __forceinline__ void st_rel(int* p, int v) {
    asm volatile("st.release.gpu.global.b32 [%0], %1;"
                 :: "l"(p), "r"(v) : "memory");
}

__global__ __launch_bounds__(256, 8)
void physics_persistent_kernel(const float* __restrict__ u_init,
                               float* __restrict__ frames,
                               int n_frames)
{
    // Edge exchange: [parity][0=first elem of warp][wid], [1=last][wid]
    __shared__ float sEdge[2][2][8];

    const int y    = blockIdx.x;          // owned row
    const int c4   = threadIdx.x;         // float4 column 0..255
    const int lane = c4 & 31;
    const int wid  = c4 >> 5;
    const int ym1  = (y - 1) & (HH - 1);
    const int yp1  = (y + 1) & (HH - 1);

    const int idx  = (y   << 8) + c4;     // float4 index within a channel
    const int idxu = (ym1 << 8) + c4;
    const int idxd = (yp1 << 8) + c4;

    int*       flag_self = &g_flags[y   * FS];
    const int* flag_up   = &g_flags[ym1 * FS];
    const int* flag_dn   = &g_flags[yp1 * FS];

    float4 u = ((const float4*)u_init)[idx];   // u_s for own row
    const float* src = u_init;                 // where u_s lives (r of s-1)
    float*       fr  = frames;                 // frame s base

    if (lane == 0)  sEdge[0][0][wid] = u.x;
    if (lane == 31) sEdge[0][1][wid] = u.w;
    __syncthreads();

    for (int s = 0; s < n_frames; ++s) {
        const float4* src4 = (const float4*)src;
        float4 hu, hd;

        if (s > 0) {
            while (ld_acq(flag_up) < s) { }
            hu = __ldcg(&src4[idxu]);          // in flight during dn spin
            while (ld_acq(flag_dn) < s) { }
            hd = __ldcg(&src4[idxd]);
        } else {
            hu = __ldcg(&src4[idxu]);
            hd = __ldcg(&src4[idxd]);
        }

        const int par = s & 1;
        const float lwS = sEdge[par][1][(wid - 1) & 7];
        const float rxS = sEdge[par][0][(wid + 1) & 7];

        float lw = __shfl_up_sync(0xffffffffu, u.w, 1);
        float rx = __shfl_down_sync(0xffffffffu, u.x, 1);
        if (lane == 0)  lw = lwS;
        if (lane == 31) rx = rxS;

        const float uc[4] = {u.x,  u.y,  u.z,  u.w};
        const float ul[4] = {lw,   u.x,  u.y,  u.z};
        const float ur[4] = {u.y,  u.z,  u.w,  rx};
        const float uu[4] = {hu.x, hu.y, hu.z, hu.w};
        const float ud[4] = {hd.x, hd.y, hd.z, hd.w};

        float4 n;
        float* np = &n.x;
        #pragma unroll
        for (int i = 0; i < 4; ++i) {
            const float lap = ul[i] + ur[i] + uu[i] + ud[i] - 4.0f * uc[i];
            float v = uc[i] + DT * (ALPHA * lap - V_X * (uc[i] - ul[i]));
            np[i] = fminf(fmaxf(v, 0.0f), 1.0f);
        }

        float4* f4 = (float4*)fr;
        f4[idx] = n;                       // r channel: the only re-read data

        // Stage next step's edges (other parity slot; race-free).
        if (lane == 0)  sEdge[par ^ 1][0][wid] = n.x;
        if (lane == 31) sEdge[par ^ 1][1][wid] = n.w;

        // Publish: barrier (all r stores + edge STS ordered) -> release.
        __syncthreads();
        if (c4 == 0) st_rel(flag_self, s + 1);

        // g/b: never read by anyone -> off the critical chain. Plain
        // writeback stores: L2 buffers the pulse and drains continuously.
        float4 t;
        t.x = n.x * 0.5f; t.y = n.y * 0.5f;
        t.z = n.z * 0.5f; t.w = n.w * 0.5f;
        f4[idx + (HW / 4)] = t;
        t.x = 1.0f - n.x; t.y = 1.0f - n.y;
        t.z = 1.0f - n.z; t.w = 1.0f - n.w;
        f4[idx + 2 * (HW / 4)] = t;

        u   = n;
        src = fr;          // r channel of frame s == u_{s+1}
        fr += 3 * HW;
    }
}

extern "C" void kernel_launch(void* const* d_in, const int* in_sizes, int n_in,
                              void* d_out, int out_size) {
    const float* init = (const float*)d_in[0];
    float* out = (float*)d_out;
    const int n_frames = out_size / (3 * HW);

    reset_flags_kernel<<<NB / 256, 256>>>();
    physics_persistent_kernel<<<NB, 256>>>(init, out, n_frames);
}